// round 12
// baseline (speedup 1.0000x reference)
#include <cuda_runtime.h>
#include <cuda_bf16.h>
#include <cstdint>
#include <math.h>

#define DEV_INLINE __device__ __forceinline__

// ---------------- problem constants ----------------
static constexpr int D_DIM = 512;
static constexpr int MAXB  = 2048;
static constexpr int MAXV  = 32000;
static constexpr float S_SCALE = 30.0f;
static constexpr float LOG2E   = 1.4426950408889634f;
static constexpr float S_LOG2E = S_SCALE * LOG2E;            // 43.2808...
static constexpr float COS_M = 0.8775825618903728f;          // cos(0.5)
static constexpr float SIN_M = 0.4794255386042030f;          // sin(0.5)

// ---------------- scratch (device globals; no cudaMalloc allowed) ----------------
__device__ __nv_bfloat16 g_nx[MAXB * D_DIM];
__device__ __nv_bfloat16 g_nW[MAXV * D_DIM];
__device__ float g_rowsum[MAXB];
__device__ float g_cosy[MAXB];
__device__ int   g_lab64;

// ---------------- PTX helpers (plain sm_103 ISA only) --------
DEV_INLINE uint32_t smem_u32(const void* p) {
    uint32_t a;
    asm("{ .reg .u64 t; cvta.to.shared.u64 t, %1; cvt.u32.u64 %0, t; }"
        : "=r"(a) : "l"(p));
    return a;
}

DEV_INLINE float ex2_fast(float x) {     // single MUFU.EX2
    float y;
    asm("ex2.approx.ftz.f32 %0, %1;" : "=f"(y) : "f"(x));
    return y;
}

DEV_INLINE void cp_async16(uint32_t saddr, const void* gptr) {
    asm volatile("cp.async.cg.shared.global [%0], [%1], 16;"
                 :: "r"(saddr), "l"(gptr) : "memory");
}
DEV_INLINE void cp_commit() { asm volatile("cp.async.commit_group;" ::: "memory"); }
template <int N>
DEV_INLINE void cp_wait() { asm volatile("cp.async.wait_group %0;" :: "n"(N) : "memory"); }

DEV_INLINE void ldsm_x4(uint32_t& r0, uint32_t& r1, uint32_t& r2, uint32_t& r3,
                        uint32_t addr) {
    asm volatile("ldmatrix.sync.aligned.m8n8.x4.shared.b16 {%0,%1,%2,%3}, [%4];"
                 : "=r"(r0), "=r"(r1), "=r"(r2), "=r"(r3) : "r"(addr));
}

DEV_INLINE void mma16816(float* c, const uint32_t* a, const uint32_t* b) {
    asm volatile(
        "mma.sync.aligned.m16n8k16.row.col.f32.bf16.bf16.f32 "
        "{%0,%1,%2,%3}, {%4,%5,%6,%7}, {%8,%9}, {%0,%1,%2,%3};"
        : "+f"(c[0]), "+f"(c[1]), "+f"(c[2]), "+f"(c[3])
        : "r"(a[0]), "r"(a[1]), "r"(a[2]), "r"(a[3]), "r"(b[0]), "r"(b[1]));
}

// ---------------- kernel 1: row-normalize fp32 -> bf16 (x and W fused) -------
__global__ void normalize_kernel(const float* __restrict__ x,
                                 const float* __restrict__ W,
                                 __nv_bfloat16* __restrict__ nx,
                                 __nv_bfloat16* __restrict__ nW,
                                 float* __restrict__ rowsum, int B) {
    int row = blockIdx.x;
    int tid = threadIdx.x;
    const float* in;
    __nv_bfloat16* out;
    int r;
    if (row < B) { in = x; out = nx; r = row; }
    else         { in = W; out = nW; r = row - B; }
    const float4 v = *(const float4*)(in + (size_t)r * D_DIM + tid * 4);
    float ss = v.x * v.x + v.y * v.y + v.z * v.z + v.w * v.w;
    #pragma unroll
    for (int o = 16; o; o >>= 1) ss += __shfl_xor_sync(0xFFFFFFFFu, ss, o);
    __shared__ float wsum[4];
    if ((tid & 31) == 0) wsum[tid >> 5] = ss;
    __syncthreads();
    float tot = wsum[0] + wsum[1] + wsum[2] + wsum[3];
    float inv = 1.0f / fmaxf(sqrtf(tot), 1e-12f);
    __nv_bfloat162 h0 = __floats2bfloat162_rn(v.x * inv, v.y * inv);
    __nv_bfloat162 h1 = __floats2bfloat162_rn(v.z * inv, v.w * inv);
    *(__nv_bfloat162*)(out + (size_t)r * D_DIM + tid * 4)     = h0;
    *(__nv_bfloat162*)(out + (size_t)r * D_DIM + tid * 4 + 2) = h1;
    if (row < B && tid == 0) rowsum[row] = 0.0f;
}

// ---------------- kernel 2: detect label dtype (int64 vs int32) ----------------
__global__ void detect_labels_kernel(const int* __restrict__ l32) {
    int t = threadIdx.x;  // 32 threads
    int v = l32[2 * t + 1];
    unsigned m = __ballot_sync(0xFFFFFFFFu, v == 0);
    if (t == 0) g_lab64 = (m == 0xFFFFFFFFu) ? 1 : 0;
}

// ---------------- kernel 3: exact fp32 cos at label column ----------------
__global__ void cosy_kernel(const float* __restrict__ x, const float* __restrict__ W,
                            const void* __restrict__ labels, float* __restrict__ cosy,
                            int B) {
    int warp = (int)((blockIdx.x * blockDim.x + threadIdx.x) >> 5);
    int lane = threadIdx.x & 31;
    if (warp >= B) return;
    long long y;
    if (g_lab64) y = ((const long long*)labels)[warp];
    else         y = (long long)((const int*)labels)[warp];
    const float* xr = x + (size_t)warp * D_DIM;
    const float* wr = W + (size_t)y * D_DIM;
    float dot = 0.f, xx = 0.f, ww = 0.f;
    #pragma unroll
    for (int i = 0; i < 4; i++) {
        int k = (lane + i * 32) * 4;
        float4 a = *(const float4*)(xr + k);
        float4 b = *(const float4*)(wr + k);
        dot += a.x * b.x + a.y * b.y + a.z * b.z + a.w * b.w;
        xx  += a.x * a.x + a.y * a.y + a.z * a.z + a.w * a.w;
        ww  += b.x * b.x + b.y * b.y + b.z * b.z + b.w * b.w;
    }
    #pragma unroll
    for (int o = 16; o; o >>= 1) {
        dot += __shfl_xor_sync(0xFFFFFFFFu, dot, o);
        xx  += __shfl_xor_sync(0xFFFFFFFFu, xx, o);
        ww  += __shfl_xor_sync(0xFFFFFFFFu, ww, o);
    }
    if (lane == 0)
        cosy[warp] = dot / (fmaxf(sqrtf(xx), 1e-12f) * fmaxf(sqrtf(ww), 1e-12f));
}

// ---------------- kernel 4: A-resident HMMA GEMM + fused exp row-sum --------
// A (128x512 bf16 = 128KB) resident; B via 3-slot x 32KB ring (KC=128 ->
// only 4 barrier/wait events per N-tile). 256 threads, 8 warps (2M x 4N),
// warp tile 64x32. 224KB smem, 1 CTA/SM.
static constexpr int TM = 128;
static constexpr int TN = 128;
static constexpr int KC = 128;                 // bf16 per chunk
static constexpr int KT = D_DIM / KC;          // 4
static constexpr int BSTAGES = 3;
static constexpr int NTHR = 256;
static constexpr int NGROUP = 9;               // 9*16 = 144 CTAs
static constexpr int A_BYTES = TM * D_DIM * 2;          // 131072
static constexpr int B_STAGE_BYTES = TN * KC * 2;       // 32768
static constexpr int SM_TOTAL = A_BYTES + BSTAGES * B_STAGE_BYTES;  // 229376

// A smem: 1024B rows (512 bf16). XOR swizzle on 16B chunks; XOR touches only
// bits 0-2 of the chunk index, so banks are conflict-free for ldmatrix.
DEV_INLINE uint32_t a_off(int row, int k) {
    return (uint32_t)(row * 1024 + (((k >> 3) ^ (row & 7)) << 4) + ((k & 7) << 1));
}
// B stage: 256B rows (KC=128 bf16), same swizzle family.
DEV_INLINE uint32_t b_off(int row, int k) {
    return (uint32_t)(row * 256 + (((k >> 3) ^ (row & 7)) << 4) + ((k & 7) << 1));
}

// load one 32KB B chunk (TN rows x KC bf16)
DEV_INLINE void load_b(uint32_t sbase, const __nv_bfloat16* __restrict__ src,
                       int n0, int k0, int tid) {
    #pragma unroll
    for (int i = 0; i < TN * (KC / 8) / NTHR; i++) {     // 8 iters
        int idx = i * NTHR + tid;
        int row = idx >> 4;
        int kc  = (idx & 15) << 3;
        cp_async16(sbase + b_off(row, kc),
                   src + (size_t)(n0 + row) * D_DIM + k0 + kc);
    }
}

__global__ void __launch_bounds__(NTHR, 1)
gemm_expsum_kernel(const __nv_bfloat16* __restrict__ A,
                   const __nv_bfloat16* __restrict__ Bm,
                   float* __restrict__ rowsum, int nvt) {
    extern __shared__ char smem[];
    const uint32_t sa = smem_u32(smem);                 // A region
    const uint32_t sbB = sa + A_BYTES;                  // B ring base
    const int tid = threadIdx.x;
    const int wid = tid >> 5, lid = tid & 31;
    const int wm = wid & 1;          // 0..1 (M, 64 rows)
    const int wn = wid >> 1;         // 0..3 (N, 32 cols)
    const int m0 = blockIdx.y * TM;

    // this CTA's N-tile range
    const int t0 = (blockIdx.x * nvt) / NGROUP;
    const int t1 = ((blockIdx.x + 1) * nvt) / NGROUP;
    if (t0 >= t1) return;

    // ---- load A tile once (128KB) ----
    #pragma unroll
    for (int i = 0; i < TM * 64 / NTHR; i++) {          // 32 iters
        int idx = i * NTHR + tid;
        int row = idx >> 6;
        int c   = idx & 63;                             // 16B chunk in row
        cp_async16(sa + a_off(row, c * 8),
                   A + (size_t)(m0 + row) * D_DIM + c * 8);
    }
    cp_commit();

    // ---- B prologue: chunks 0,1 of first tile ----
    int n0 = t0 * TN;
    #pragma unroll
    for (int s = 0; s < BSTAGES - 1; s++) {
        load_b(sbB + s * B_STAGE_BYTES, Bm, n0, s * KC, tid);
        cp_commit();
    }

    // per-lane ldmatrix coordinates
    const int a_row = wm * 64 + (lid & 15);   // + mt*16
    const int a_kc  = (lid >> 4) << 3;        // 0/8, + kt*128 + ks*16
    const int b_row = wn * 32 + (lid & 15);   // + np*16
    const int b_kc  = (lid >> 4) << 3;

    float acc[4][4][4];
    #pragma unroll
    for (int i = 0; i < 4; i++)
        #pragma unroll
        for (int j = 0; j < 4; j++)
            #pragma unroll
            for (int q = 0; q < 4; q++) acc[i][j][q] = 0.f;

    int slot = 0;  // ring slot of the chunk being consumed
    for (int t = t0; t < t1; t++) {
        const int nn0 = (t + 1 < t1) ? (t + 1) * TN : -1;
        #pragma unroll
        for (int kt = 0; kt < KT; kt++) {
            cp_wait<BSTAGES - 2>();     // chunk (t,kt) resident (this thread)
            __syncthreads();            // all threads; prior slot reads done

            // prefetch chunk +2 into the slot read in the previous iteration
            int ps = (slot + BSTAGES - 1) % BSTAGES;
            if (kt + BSTAGES - 1 < KT) {
                load_b(sbB + ps * B_STAGE_BYTES, Bm, n0, (kt + BSTAGES - 1) * KC, tid);
            } else if (nn0 >= 0) {
                load_b(sbB + ps * B_STAGE_BYTES, Bm, nn0, (kt + BSTAGES - 1 - KT) * KC, tid);
            }
            cp_commit();                // one group per iteration, always

            const uint32_t sbm = sbB + slot * B_STAGE_BYTES;
            const int kbase = kt * KC;

            #pragma unroll
            for (int ks = 0; ks < KC / 16; ks++) {       // 8 steps
                uint32_t afr[4][4];
                #pragma unroll
                for (int mt = 0; mt < 4; mt++)
                    ldsm_x4(afr[mt][0], afr[mt][1], afr[mt][2], afr[mt][3],
                            sa + a_off(a_row + mt * 16, kbase + ks * 16 + a_kc));
                uint32_t bfr[2][4];
                #pragma unroll
                for (int np = 0; np < 2; np++)
                    ldsm_x4(bfr[np][0], bfr[np][1], bfr[np][2], bfr[np][3],
                            sbm + b_off(b_row + np * 16, ks * 16 + b_kc));
                #pragma unroll
                for (int mt = 0; mt < 4; mt++)
                    #pragma unroll
                    for (int nt = 0; nt < 4; nt++)
                        mma16816(acc[mt][nt], afr[mt], &bfr[nt >> 1][(nt & 1) * 2]);
            }
            slot = (slot + 1) % BSTAGES;
        }

        // Epilogue: single-MUFU ex2 per value (next tile's B streams meanwhile)
        #pragma unroll
        for (int mt = 0; mt < 4; mt++) {
            float s0 = 0.f, s1 = 0.f;
            #pragma unroll
            for (int nt = 0; nt < 4; nt++) {
                s0 += ex2_fast(acc[mt][nt][0] * S_LOG2E)
                    + ex2_fast(acc[mt][nt][1] * S_LOG2E);
                s1 += ex2_fast(acc[mt][nt][2] * S_LOG2E)
                    + ex2_fast(acc[mt][nt][3] * S_LOG2E);
                #pragma unroll
                for (int q = 0; q < 4; q++) acc[mt][nt][q] = 0.f;
            }
            s0 += __shfl_xor_sync(0xFFFFFFFFu, s0, 1);
            s0 += __shfl_xor_sync(0xFFFFFFFFu, s0, 2);
            s1 += __shfl_xor_sync(0xFFFFFFFFu, s1, 1);
            s1 += __shfl_xor_sync(0xFFFFFFFFu, s1, 2);
            if ((lid & 3) == 0) {
                int r = m0 + wm * 64 + mt * 16 + (lid >> 2);
                atomicAdd(&rowsum[r], s0);
                atomicAdd(&rowsum[r + 8], s1);
            }
        }
        n0 = nn0;
    }
}

// ---------------- kernel 5: finalize ----------------
__global__ void finalize_kernel(const float* __restrict__ rowsum,
                                const float* __restrict__ cosy,
                                float* __restrict__ out, int B) {
    __shared__ float red[1024];
    int tid = threadIdx.x;
    float local = 0.f;
    for (int b = tid; b < B; b += blockDim.x) {
        float c  = fminf(fmaxf(cosy[b], -1.f), 1.f);
        float sn = sqrtf(fmaxf(1.f - c * c, 0.f));
        float phi = c * COS_M - sn * SIN_M;
        float S = rowsum[b] - exp2f(S_LOG2E * c) + exp2f(S_LOG2E * phi);
        local += logf(S) - S_SCALE * phi;
    }
    red[tid] = local;
    __syncthreads();
    #pragma unroll
    for (int s = 512; s > 0; s >>= 1) {
        if (tid < s) red[tid] += red[tid + s];
        __syncthreads();
    }
    if (tid == 0) out[0] = red[0] / (float)B;
}

// ---------------- launch ----------------
extern "C" void kernel_launch(void* const* d_in, const int* in_sizes, int n_in,
                              void* d_out, int out_size) {
    const float* x = (const float*)d_in[0];
    const float* W = (const float*)d_in[1];
    const void*  labels = d_in[2];
    float* out = (float*)d_out;

    int B = in_sizes[0] / D_DIM;
    int V = in_sizes[1] / D_DIM;
    int nvt = V / TN;                           // 250

    __nv_bfloat16 *nx, *nW;
    float *rowsum, *cosy;
    cudaGetSymbolAddress((void**)&nx, g_nx);
    cudaGetSymbolAddress((void**)&nW, g_nW);
    cudaGetSymbolAddress((void**)&rowsum, g_rowsum);
    cudaGetSymbolAddress((void**)&cosy, g_cosy);

    cudaFuncSetAttribute(gemm_expsum_kernel,
                         cudaFuncAttributeMaxDynamicSharedMemorySize, SM_TOTAL);

    normalize_kernel<<<B + V, 128>>>(x, W, nx, nW, rowsum, B);
    detect_labels_kernel<<<1, 32>>>((const int*)labels);
    gemm_expsum_kernel<<<dim3(NGROUP, B / TM), NTHR, SM_TOTAL>>>(nx, nW, rowsum, nvt);
    cosy_kernel<<<(B + 7) / 8, 256>>>(x, W, labels, cosy, B);
    finalize_kernel<<<1, 1024>>>(rowsum, cosy, out, B);
}

// round 13
// speedup vs baseline: 1.0111x; 1.0111x over previous
#include <cuda_runtime.h>
#include <cuda_bf16.h>
#include <cstdint>
#include <math.h>

#define DEV_INLINE __device__ __forceinline__

// ---------------- problem constants ----------------
static constexpr int D_DIM = 512;
static constexpr int MAXB  = 2048;
static constexpr int MAXV  = 32000;
static constexpr float S_SCALE = 30.0f;
static constexpr float LOG2E   = 1.4426950408889634f;
static constexpr float S_LOG2E = S_SCALE * LOG2E;            // 43.2808...
static constexpr float COS_M = 0.8775825618903728f;          // cos(0.5)
static constexpr float SIN_M = 0.4794255386042030f;          // sin(0.5)

// ---------------- scratch (device globals; no cudaMalloc allowed) ----------------
__device__ __nv_bfloat16 g_nx[MAXB * D_DIM];
__device__ __nv_bfloat16 g_nW[MAXV * D_DIM];
__device__ float g_rowsum[MAXB];
__device__ float g_cosy[MAXB];
__device__ int   g_lab64;

// ---------------- PTX helpers (plain sm_103 ISA only) --------
DEV_INLINE uint32_t smem_u32(const void* p) {
    uint32_t a;
    asm("{ .reg .u64 t; cvta.to.shared.u64 t, %1; cvt.u32.u64 %0, t; }"
        : "=r"(a) : "l"(p));
    return a;
}

DEV_INLINE float ex2_fast(float x) {     // single MUFU.EX2
    float y;
    asm("ex2.approx.ftz.f32 %0, %1;" : "=f"(y) : "f"(x));
    return y;
}

DEV_INLINE void cp_async16(uint32_t saddr, const void* gptr) {
    asm volatile("cp.async.cg.shared.global [%0], [%1], 16;"
                 :: "r"(saddr), "l"(gptr) : "memory");
}
DEV_INLINE void cp_commit() { asm volatile("cp.async.commit_group;" ::: "memory"); }
template <int N>
DEV_INLINE void cp_wait() { asm volatile("cp.async.wait_group %0;" :: "n"(N) : "memory"); }

DEV_INLINE void ldsm_x4(uint32_t& r0, uint32_t& r1, uint32_t& r2, uint32_t& r3,
                        uint32_t addr) {
    asm volatile("ldmatrix.sync.aligned.m8n8.x4.shared.b16 {%0,%1,%2,%3}, [%4];"
                 : "=r"(r0), "=r"(r1), "=r"(r2), "=r"(r3) : "r"(addr));
}

DEV_INLINE void mma16816(float* c, const uint32_t* a, const uint32_t* b) {
    asm volatile(
        "mma.sync.aligned.m16n8k16.row.col.f32.bf16.bf16.f32 "
        "{%0,%1,%2,%3}, {%4,%5,%6,%7}, {%8,%9}, {%0,%1,%2,%3};"
        : "+f"(c[0]), "+f"(c[1]), "+f"(c[2]), "+f"(c[3])
        : "r"(a[0]), "r"(a[1]), "r"(a[2]), "r"(a[3]), "r"(b[0]), "r"(b[1]));
}

// ---------------- kernel 1: normalize (x & W) + label-dtype detect ----------
__global__ void normalize_kernel(const float* __restrict__ x,
                                 const float* __restrict__ W,
                                 __nv_bfloat16* __restrict__ nx,
                                 __nv_bfloat16* __restrict__ nW,
                                 float* __restrict__ rowsum,
                                 const int* __restrict__ l32, int B, int V) {
    int row = blockIdx.x;
    int tid = threadIdx.x;
    if (row == B + V) {                 // label dtype detection block
        if (tid < 32) {
            int v = l32[2 * tid + 1];
            unsigned m = __ballot_sync(0xFFFFFFFFu, v == 0);
            if (tid == 0) g_lab64 = (m == 0xFFFFFFFFu) ? 1 : 0;
        }
        return;
    }
    const float* in;
    __nv_bfloat16* out;
    int r;
    if (row < B) { in = x; out = nx; r = row; }
    else         { in = W; out = nW; r = row - B; }
    const float4 v = *(const float4*)(in + (size_t)r * D_DIM + tid * 4);
    float ss = v.x * v.x + v.y * v.y + v.z * v.z + v.w * v.w;
    #pragma unroll
    for (int o = 16; o; o >>= 1) ss += __shfl_xor_sync(0xFFFFFFFFu, ss, o);
    __shared__ float wsum[4];
    if ((tid & 31) == 0) wsum[tid >> 5] = ss;
    __syncthreads();
    float tot = wsum[0] + wsum[1] + wsum[2] + wsum[3];
    float inv = 1.0f / fmaxf(sqrtf(tot), 1e-12f);
    __nv_bfloat162 h0 = __floats2bfloat162_rn(v.x * inv, v.y * inv);
    __nv_bfloat162 h1 = __floats2bfloat162_rn(v.z * inv, v.w * inv);
    *(__nv_bfloat162*)(out + (size_t)r * D_DIM + tid * 4)     = h0;
    *(__nv_bfloat162*)(out + (size_t)r * D_DIM + tid * 4 + 2) = h1;
    if (row < B && tid == 0) rowsum[row] = 0.0f;
}

// ---------------- kernel 3: exact fp32 cos at label column ----------------
__global__ void cosy_kernel(const float* __restrict__ x, const float* __restrict__ W,
                            const void* __restrict__ labels, float* __restrict__ cosy,
                            int B) {
    int warp = (int)((blockIdx.x * blockDim.x + threadIdx.x) >> 5);
    int lane = threadIdx.x & 31;
    if (warp >= B) return;
    long long y;
    if (g_lab64) y = ((const long long*)labels)[warp];
    else         y = (long long)((const int*)labels)[warp];
    const float* xr = x + (size_t)warp * D_DIM;
    const float* wr = W + (size_t)y * D_DIM;
    float dot = 0.f, xx = 0.f, ww = 0.f;
    #pragma unroll
    for (int i = 0; i < 4; i++) {
        int k = (lane + i * 32) * 4;
        float4 a = *(const float4*)(xr + k);
        float4 b = *(const float4*)(wr + k);
        dot += a.x * b.x + a.y * b.y + a.z * b.z + a.w * b.w;
        xx  += a.x * a.x + a.y * a.y + a.z * a.z + a.w * a.w;
        ww  += b.x * b.x + b.y * b.y + b.z * b.z + b.w * b.w;
    }
    #pragma unroll
    for (int o = 16; o; o >>= 1) {
        dot += __shfl_xor_sync(0xFFFFFFFFu, dot, o);
        xx  += __shfl_xor_sync(0xFFFFFFFFu, xx, o);
        ww  += __shfl_xor_sync(0xFFFFFFFFu, ww, o);
    }
    if (lane == 0)
        cosy[warp] = dot / (fmaxf(sqrtf(xx), 1e-12f) * fmaxf(sqrtf(ww), 1e-12f));
}

// ---------------- kernel 4: A-resident HMMA GEMM + fused exp row-sum --------
// A (128x512 bf16 = 128KB) resident; B via 3-slot x 32KB ring; KC=64.
// 512 threads, 16 warps (2M x 8N), warp tile 64x32 -> 4 warps/SMSP for
// latency hiding. TN=256 -> 125 N-tiles/row, 9 CTAs -> 13/14 tiles each.
static constexpr int TM = 128;
static constexpr int TN = 256;
static constexpr int KC = 64;
static constexpr int KT = D_DIM / KC;          // 8
static constexpr int BSTAGES = 3;
static constexpr int NTHR = 512;
static constexpr int NGROUP = 9;               // 9*16 = 144 CTAs
static constexpr int A_BYTES = TM * D_DIM * 2;          // 131072
static constexpr int B_STAGE_BYTES = TN * KC * 2;       // 32768
static constexpr int SM_TOTAL = A_BYTES + BSTAGES * B_STAGE_BYTES;  // 229376

// A smem: 1024B rows (512 bf16), XOR swizzle on 16B chunks (conflict-free).
DEV_INLINE uint32_t a_off(int row, int k) {
    return (uint32_t)(row * 1024 + (((k >> 3) ^ (row & 7)) << 4) + ((k & 7) << 1));
}
// B stage: 128B rows (KC=64 bf16), same swizzle family.
DEV_INLINE uint32_t sw_off(int row, int k) {
    return (uint32_t)(row * 128 + (((k >> 3) ^ (row & 7)) << 4) + ((k & 7) << 1));
}

// load one 32KB B chunk (TN=256 rows x KC=64 bf16)
DEV_INLINE void load_b(uint32_t sbase, const __nv_bfloat16* __restrict__ src,
                       int n0, int k0, int tid) {
    #pragma unroll
    for (int i = 0; i < TN * 8 / NTHR; i++) {      // 4 iters
        int idx = i * NTHR + tid;
        int row = idx >> 3;
        int kc  = (idx & 7) << 3;
        cp_async16(sbase + sw_off(row, kc),
                   src + (size_t)(n0 + row) * D_DIM + k0 + kc);
    }
}

__global__ void __launch_bounds__(NTHR, 1)
gemm_expsum_kernel(const __nv_bfloat16* __restrict__ A,
                   const __nv_bfloat16* __restrict__ Bm,
                   float* __restrict__ rowsum, int nvt) {
    extern __shared__ char smem[];
    const uint32_t sa = smem_u32(smem);                 // A region
    const uint32_t sbB = sa + A_BYTES;                  // B ring base
    const int tid = threadIdx.x;
    const int wid = tid >> 5, lid = tid & 31;
    const int wm = wid & 1;          // 0..1 (M, 64 rows)
    const int wn = wid >> 1;         // 0..7 (N, 32 cols)
    const int m0 = blockIdx.y * TM;

    // this CTA's N-tile range
    const int t0 = (blockIdx.x * nvt) / NGROUP;
    const int t1 = ((blockIdx.x + 1) * nvt) / NGROUP;
    if (t0 >= t1) return;

    // ---- load A tile once (128KB) ----
    #pragma unroll
    for (int i = 0; i < TM * 64 / NTHR; i++) {          // 16 iters
        int idx = i * NTHR + tid;
        int row = idx >> 6;
        int c   = idx & 63;                             // 16B chunk in row
        cp_async16(sa + a_off(row, c * 8),
                   A + (size_t)(m0 + row) * D_DIM + c * 8);
    }
    cp_commit();

    // ---- B prologue: chunks 0,1 of first tile ----
    int n0 = t0 * TN;
    #pragma unroll
    for (int s = 0; s < BSTAGES - 1; s++) {
        load_b(sbB + s * B_STAGE_BYTES, Bm, n0, s * KC, tid);
        cp_commit();
    }

    // per-lane ldmatrix coordinates
    const int a_row = wm * 64 + (lid & 15);   // + mt*16
    const int a_kc  = (lid >> 4) << 3;        // 0/8, + kt*64 + ks*16
    const int b_row = wn * 32 + (lid & 15);   // + np*16
    const int b_kc  = (lid >> 4) << 3;

    float acc[4][4][4];
    #pragma unroll
    for (int i = 0; i < 4; i++)
        #pragma unroll
        for (int j = 0; j < 4; j++)
            #pragma unroll
            for (int q = 0; q < 4; q++) acc[i][j][q] = 0.f;

    int slot = 0;  // ring slot of the chunk being consumed
    for (int t = t0; t < t1; t++) {
        const int nn0 = (t + 1 < t1) ? (t + 1) * TN : -1;
        #pragma unroll
        for (int kt = 0; kt < KT; kt++) {
            cp_wait<BSTAGES - 2>();     // chunk (t,kt) resident (this thread)
            __syncthreads();            // all threads; prior slot reads done

            // prefetch chunk +2 into the slot read in the previous iteration
            int ps = (slot + BSTAGES - 1) % BSTAGES;
            if (kt + BSTAGES - 1 < KT) {
                load_b(sbB + ps * B_STAGE_BYTES, Bm, n0, (kt + BSTAGES - 1) * KC, tid);
            } else if (nn0 >= 0) {
                load_b(sbB + ps * B_STAGE_BYTES, Bm, nn0, (kt + BSTAGES - 1 - KT) * KC, tid);
            }
            cp_commit();                // one group per iteration, always

            const uint32_t sbm = sbB + slot * B_STAGE_BYTES;
            const int kbase = kt * KC;

            #pragma unroll
            for (int ks = 0; ks < KC / 16; ks++) {
                uint32_t afr[4][4];
                #pragma unroll
                for (int mt = 0; mt < 4; mt++)
                    ldsm_x4(afr[mt][0], afr[mt][1], afr[mt][2], afr[mt][3],
                            sa + a_off(a_row + mt * 16, kbase + ks * 16 + a_kc));
                uint32_t bfr[2][4];
                #pragma unroll
                for (int np = 0; np < 2; np++)
                    ldsm_x4(bfr[np][0], bfr[np][1], bfr[np][2], bfr[np][3],
                            sbm + sw_off(b_row + np * 16, ks * 16 + b_kc));
                #pragma unroll
                for (int mt = 0; mt < 4; mt++)
                    #pragma unroll
                    for (int nt = 0; nt < 4; nt++)
                        mma16816(acc[mt][nt], afr[mt], &bfr[nt >> 1][(nt & 1) * 2]);
            }
            slot = (slot + 1) % BSTAGES;
        }

        // Epilogue: single-MUFU ex2 per value (next tile's B streams meanwhile)
        #pragma unroll
        for (int mt = 0; mt < 4; mt++) {
            float s0 = 0.f, s1 = 0.f;
            #pragma unroll
            for (int nt = 0; nt < 4; nt++) {
                s0 += ex2_fast(acc[mt][nt][0] * S_LOG2E)
                    + ex2_fast(acc[mt][nt][1] * S_LOG2E);
                s1 += ex2_fast(acc[mt][nt][2] * S_LOG2E)
                    + ex2_fast(acc[mt][nt][3] * S_LOG2E);
                #pragma unroll
                for (int q = 0; q < 4; q++) acc[mt][nt][q] = 0.f;
            }
            s0 += __shfl_xor_sync(0xFFFFFFFFu, s0, 1);
            s0 += __shfl_xor_sync(0xFFFFFFFFu, s0, 2);
            s1 += __shfl_xor_sync(0xFFFFFFFFu, s1, 1);
            s1 += __shfl_xor_sync(0xFFFFFFFFu, s1, 2);
            if ((lid & 3) == 0) {
                int r = m0 + wm * 64 + mt * 16 + (lid >> 2);
                atomicAdd(&rowsum[r], s0);
                atomicAdd(&rowsum[r + 8], s1);
            }
        }
        n0 = nn0;
    }
}

// ---------------- kernel 5: finalize ----------------
__global__ void finalize_kernel(const float* __restrict__ rowsum,
                                const float* __restrict__ cosy,
                                float* __restrict__ out, int B) {
    __shared__ float red[1024];
    int tid = threadIdx.x;
    float local = 0.f;
    for (int b = tid; b < B; b += blockDim.x) {
        float c  = fminf(fmaxf(cosy[b], -1.f), 1.f);
        float sn = sqrtf(fmaxf(1.f - c * c, 0.f));
        float phi = c * COS_M - sn * SIN_M;
        float S = rowsum[b] - exp2f(S_LOG2E * c) + exp2f(S_LOG2E * phi);
        local += logf(S) - S_SCALE * phi;
    }
    red[tid] = local;
    __syncthreads();
    #pragma unroll
    for (int s = 512; s > 0; s >>= 1) {
        if (tid < s) red[tid] += red[tid + s];
        __syncthreads();
    }
    if (tid == 0) out[0] = red[0] / (float)B;
}

// ---------------- launch ----------------
extern "C" void kernel_launch(void* const* d_in, const int* in_sizes, int n_in,
                              void* d_out, int out_size) {
    const float* x = (const float*)d_in[0];
    const float* W = (const float*)d_in[1];
    const void*  labels = d_in[2];
    float* out = (float*)d_out;

    int B = in_sizes[0] / D_DIM;
    int V = in_sizes[1] / D_DIM;
    int nvt = V / TN;                           // 125

    __nv_bfloat16 *nx, *nW;
    float *rowsum, *cosy;
    cudaGetSymbolAddress((void**)&nx, g_nx);
    cudaGetSymbolAddress((void**)&nW, g_nW);
    cudaGetSymbolAddress((void**)&rowsum, g_rowsum);
    cudaGetSymbolAddress((void**)&cosy, g_cosy);

    cudaFuncSetAttribute(gemm_expsum_kernel,
                         cudaFuncAttributeMaxDynamicSharedMemorySize, SM_TOTAL);

    normalize_kernel<<<B + V + 1, 128>>>(x, W, nx, nW, rowsum,
                                         (const int*)labels, B, V);
    gemm_expsum_kernel<<<dim3(NGROUP, B / TM), NTHR, SM_TOTAL>>>(nx, nW, rowsum, nvt);
    cosy_kernel<<<(B + 7) / 8, 256>>>(x, W, labels, cosy, B);
    finalize_kernel<<<1, 1024>>>(rowsum, cosy, out, B);
}

// round 14
// speedup vs baseline: 1.1038x; 1.0918x over previous
#include <cuda_runtime.h>
#include <cuda_bf16.h>
#include <cstdint>
#include <math.h>

#define DEV_INLINE __device__ __forceinline__

// ---------------- problem constants ----------------
static constexpr int D_DIM = 512;
static constexpr int MAXB  = 2048;
static constexpr int MAXV  = 32000;
static constexpr float S_SCALE = 30.0f;
static constexpr float LOG2E   = 1.4426950408889634f;
static constexpr float S_LOG2E = S_SCALE * LOG2E;            // 43.2808...
static constexpr float COS_M = 0.8775825618903728f;          // cos(0.5)
static constexpr float SIN_M = 0.4794255386042030f;          // sin(0.5)

// ---------------- scratch (device globals; no cudaMalloc allowed) ----------------
__device__ __nv_bfloat16 g_nx[MAXB * D_DIM];
__device__ __nv_bfloat16 g_nW[MAXV * D_DIM];
__device__ float g_rowsum[MAXB];
__device__ float g_xinv[MAXB];
__device__ float g_winv[MAXV];
__device__ int   g_lab64;

// ---------------- PTX helpers (plain sm_103 ISA only) --------
DEV_INLINE uint32_t smem_u32(const void* p) {
    uint32_t a;
    asm("{ .reg .u64 t; cvta.to.shared.u64 t, %1; cvt.u32.u64 %0, t; }"
        : "=r"(a) : "l"(p));
    return a;
}

DEV_INLINE float ex2_fast(float x) {     // single MUFU.EX2
    float y;
    asm("ex2.approx.ftz.f32 %0, %1;" : "=f"(y) : "f"(x));
    return y;
}

DEV_INLINE void cp_async16(uint32_t saddr, const void* gptr) {
    asm volatile("cp.async.cg.shared.global [%0], [%1], 16;"
                 :: "r"(saddr), "l"(gptr) : "memory");
}
DEV_INLINE void cp_commit() { asm volatile("cp.async.commit_group;" ::: "memory"); }
template <int N>
DEV_INLINE void cp_wait() { asm volatile("cp.async.wait_group %0;" :: "n"(N) : "memory"); }

DEV_INLINE void ldsm_x4(uint32_t& r0, uint32_t& r1, uint32_t& r2, uint32_t& r3,
                        uint32_t addr) {
    asm volatile("ldmatrix.sync.aligned.m8n8.x4.shared.b16 {%0,%1,%2,%3}, [%4];"
                 : "=r"(r0), "=r"(r1), "=r"(r2), "=r"(r3) : "r"(addr));
}

DEV_INLINE void mma16816(float* c, const uint32_t* a, const uint32_t* b) {
    asm volatile(
        "mma.sync.aligned.m16n8k16.row.col.f32.bf16.bf16.f32 "
        "{%0,%1,%2,%3}, {%4,%5,%6,%7}, {%8,%9}, {%0,%1,%2,%3};"
        : "+f"(c[0]), "+f"(c[1]), "+f"(c[2]), "+f"(c[3])
        : "r"(a[0]), "r"(a[1]), "r"(a[2]), "r"(a[3]), "r"(b[0]), "r"(b[1]));
}

// ---------------- kernel 1: normalize (x & W) + inv norms + misc init --------
__global__ void normalize_kernel(const float* __restrict__ x,
                                 const float* __restrict__ W,
                                 __nv_bfloat16* __restrict__ nx,
                                 __nv_bfloat16* __restrict__ nW,
                                 float* __restrict__ rowsum,
                                 float* __restrict__ xinv,
                                 float* __restrict__ winv,
                                 const int* __restrict__ l32,
                                 float* __restrict__ out, int B, int V) {
    int row = blockIdx.x;
    int tid = threadIdx.x;
    if (row == B + V) {                 // misc block: label dtype + out zero
        if (tid < 32) {
            int v = l32[2 * tid + 1];
            unsigned m = __ballot_sync(0xFFFFFFFFu, v == 0);
            if (tid == 0) g_lab64 = (m == 0xFFFFFFFFu) ? 1 : 0;
        }
        if (tid == 32) out[0] = 0.0f;
        return;
    }
    const float* in;
    __nv_bfloat16* outp;
    int r;
    if (row < B) { in = x; outp = nx; r = row; }
    else         { in = W; outp = nW; r = row - B; }
    const float4 v = *(const float4*)(in + (size_t)r * D_DIM + tid * 4);
    float ss = v.x * v.x + v.y * v.y + v.z * v.z + v.w * v.w;
    #pragma unroll
    for (int o = 16; o; o >>= 1) ss += __shfl_xor_sync(0xFFFFFFFFu, ss, o);
    __shared__ float wsum[4];
    if ((tid & 31) == 0) wsum[tid >> 5] = ss;
    __syncthreads();
    float tot = wsum[0] + wsum[1] + wsum[2] + wsum[3];
    float inv = 1.0f / fmaxf(sqrtf(tot), 1e-12f);
    __nv_bfloat162 h0 = __floats2bfloat162_rn(v.x * inv, v.y * inv);
    __nv_bfloat162 h1 = __floats2bfloat162_rn(v.z * inv, v.w * inv);
    *(__nv_bfloat162*)(outp + (size_t)r * D_DIM + tid * 4)     = h0;
    *(__nv_bfloat162*)(outp + (size_t)r * D_DIM + tid * 4 + 2) = h1;
    if (tid == 0) {
        if (row < B) { xinv[row] = inv; rowsum[row] = 0.0f; }
        else         { winv[r] = inv; }
    }
}

// ---------------- kernel 2 (R11 GEMM, unchanged): A-resident HMMA ----------
static constexpr int TM = 128;
static constexpr int TN = 128;
static constexpr int KC = 64;
static constexpr int KT = D_DIM / KC;          // 8
static constexpr int BSTAGES = 4;
static constexpr int NTHR = 256;
static constexpr int NGROUP = 9;               // 9*16 = 144 CTAs
static constexpr int A_BYTES = TM * D_DIM * 2;          // 131072
static constexpr int B_STAGE_BYTES = TN * KC * 2;       // 16384
static constexpr int SM_TOTAL = A_BYTES + BSTAGES * B_STAGE_BYTES;  // 196608

DEV_INLINE uint32_t a_off(int row, int k) {
    return (uint32_t)(row * 1024 + (((k >> 3) ^ (row & 7)) << 4) + ((k & 7) << 1));
}
DEV_INLINE uint32_t sw_off(int row, int k) {
    return (uint32_t)(row * 128 + (((k >> 3) ^ (row & 7)) << 4) + ((k & 7) << 1));
}

DEV_INLINE void load_b(uint32_t sbase, const __nv_bfloat16* __restrict__ src,
                       int n0, int k0, int tid) {
    #pragma unroll
    for (int i = 0; i < TN * 8 / NTHR; i++) {      // 4 iters
        int idx = i * NTHR + tid;
        int row = idx >> 3;
        int kc  = (idx & 7) << 3;
        cp_async16(sbase + sw_off(row, kc),
                   src + (size_t)(n0 + row) * D_DIM + k0 + kc);
    }
}

__global__ void __launch_bounds__(NTHR, 1)
gemm_expsum_kernel(const __nv_bfloat16* __restrict__ A,
                   const __nv_bfloat16* __restrict__ Bm,
                   float* __restrict__ rowsum, int nvt) {
    extern __shared__ char smem[];
    const uint32_t sa = smem_u32(smem);                 // A region
    const uint32_t sbB = sa + A_BYTES;                  // B ring base
    const int tid = threadIdx.x;
    const int wid = tid >> 5, lid = tid & 31;
    const int wm = wid & 1;          // 0..1 (M, 64 rows)
    const int wn = wid >> 1;         // 0..3 (N, 32 cols)
    const int m0 = blockIdx.y * TM;

    const int t0 = (blockIdx.x * nvt) / NGROUP;
    const int t1 = ((blockIdx.x + 1) * nvt) / NGROUP;
    if (t0 >= t1) return;

    // ---- load A tile once (128KB) ----
    #pragma unroll
    for (int i = 0; i < TM * 64 / NTHR; i++) {          // 32 iters
        int idx = i * NTHR + tid;
        int row = idx >> 6;
        int c   = idx & 63;
        cp_async16(sa + a_off(row, c * 8),
                   A + (size_t)(m0 + row) * D_DIM + c * 8);
    }
    cp_commit();

    // ---- B prologue: chunks 0,1,2 of first tile ----
    int n0 = t0 * TN;
    #pragma unroll
    for (int s = 0; s < BSTAGES - 1; s++) {
        load_b(sbB + s * B_STAGE_BYTES, Bm, n0, s * KC, tid);
        cp_commit();
    }

    const int a_row = wm * 64 + (lid & 15);
    const int a_kc  = (lid >> 4) << 3;
    const int b_row = wn * 32 + (lid & 15);
    const int b_kc  = (lid >> 4) << 3;

    float acc[4][4][4];
    #pragma unroll
    for (int i = 0; i < 4; i++)
        #pragma unroll
        for (int j = 0; j < 4; j++)
            #pragma unroll
            for (int q = 0; q < 4; q++) acc[i][j][q] = 0.f;

    int slot = 0;
    for (int t = t0; t < t1; t++) {
        const int nn0 = (t + 1 < t1) ? (t + 1) * TN : -1;
        #pragma unroll
        for (int kt = 0; kt < KT; kt++) {
            cp_wait<BSTAGES - 2>();
            __syncthreads();

            int ps = (slot + BSTAGES - 1) & (BSTAGES - 1);
            if (kt + BSTAGES - 1 < KT) {
                load_b(sbB + ps * B_STAGE_BYTES, Bm, n0, (kt + BSTAGES - 1) * KC, tid);
            } else if (nn0 >= 0) {
                load_b(sbB + ps * B_STAGE_BYTES, Bm, nn0, (kt + BSTAGES - 1 - KT) * KC, tid);
            }
            cp_commit();

            const uint32_t sbm = sbB + slot * B_STAGE_BYTES;
            const int kbase = kt * KC;

            #pragma unroll
            for (int ks = 0; ks < KC / 16; ks++) {
                uint32_t afr[4][4];
                #pragma unroll
                for (int mt = 0; mt < 4; mt++)
                    ldsm_x4(afr[mt][0], afr[mt][1], afr[mt][2], afr[mt][3],
                            sa + a_off(a_row + mt * 16, kbase + ks * 16 + a_kc));
                uint32_t bfr[2][4];
                #pragma unroll
                for (int np = 0; np < 2; np++)
                    ldsm_x4(bfr[np][0], bfr[np][1], bfr[np][2], bfr[np][3],
                            sbm + sw_off(b_row + np * 16, ks * 16 + b_kc));
                #pragma unroll
                for (int mt = 0; mt < 4; mt++)
                    #pragma unroll
                    for (int nt = 0; nt < 4; nt++)
                        mma16816(acc[mt][nt], afr[mt], &bfr[nt >> 1][(nt & 1) * 2]);
            }
            slot = (slot + 1) & (BSTAGES - 1);
        }

        #pragma unroll
        for (int mt = 0; mt < 4; mt++) {
            float s0 = 0.f, s1 = 0.f;
            #pragma unroll
            for (int nt = 0; nt < 4; nt++) {
                s0 += ex2_fast(acc[mt][nt][0] * S_LOG2E)
                    + ex2_fast(acc[mt][nt][1] * S_LOG2E);
                s1 += ex2_fast(acc[mt][nt][2] * S_LOG2E)
                    + ex2_fast(acc[mt][nt][3] * S_LOG2E);
                #pragma unroll
                for (int q = 0; q < 4; q++) acc[mt][nt][q] = 0.f;
            }
            s0 += __shfl_xor_sync(0xFFFFFFFFu, s0, 1);
            s0 += __shfl_xor_sync(0xFFFFFFFFu, s0, 2);
            s1 += __shfl_xor_sync(0xFFFFFFFFu, s1, 1);
            s1 += __shfl_xor_sync(0xFFFFFFFFu, s1, 2);
            if ((lid & 3) == 0) {
                int r = m0 + wm * 64 + mt * 16 + (lid >> 2);
                atomicAdd(&rowsum[r], s0);
                atomicAdd(&rowsum[r + 8], s1);
            }
        }
        n0 = nn0;
    }
}

// ---------------- kernel 3: fused label-cos + loss reduction ----------------
// One warp per row: exact fp32 dot(x_b, W_y) (single reduction; inv norms
// precomputed), per-row loss, block reduce, one atomicAdd per block.
__global__ void loss_kernel(const float* __restrict__ x, const float* __restrict__ W,
                            const void* __restrict__ labels,
                            const float* __restrict__ rowsum,
                            const float* __restrict__ xinv,
                            const float* __restrict__ winv,
                            float* __restrict__ out, int B) {
    int warp = (int)((blockIdx.x * blockDim.x + threadIdx.x) >> 5);
    int lane = threadIdx.x & 31;
    int wloc = (int)(threadIdx.x >> 5);
    float contrib = 0.f;
    if (warp < B) {
        long long y;
        if (g_lab64) y = ((const long long*)labels)[warp];
        else         y = (long long)((const int*)labels)[warp];
        const float* xr = x + (size_t)warp * D_DIM;
        const float* wr = W + (size_t)y * D_DIM;
        float dot = 0.f;
        #pragma unroll
        for (int i = 0; i < 4; i++) {
            int k = (lane + i * 32) * 4;
            float4 a = *(const float4*)(xr + k);
            float4 b = *(const float4*)(wr + k);
            dot += a.x * b.x + a.y * b.y + a.z * b.z + a.w * b.w;
        }
        #pragma unroll
        for (int o = 16; o; o >>= 1)
            dot += __shfl_xor_sync(0xFFFFFFFFu, dot, o);
        if (lane == 0) {
            float c = dot * xinv[warp] * winv[(int)y];
            c = fminf(fmaxf(c, -1.f), 1.f);
            float sn = sqrtf(fmaxf(1.f - c * c, 0.f));
            float phi = c * COS_M - sn * SIN_M;
            float S = rowsum[warp] - exp2f(S_LOG2E * c) + exp2f(S_LOG2E * phi);
            contrib = logf(S) - S_SCALE * phi;
        }
    }
    // block reduce (8 warps, lane-0 values)
    __shared__ float red[8];
    if (lane == 0) red[wloc] = contrib;
    __syncthreads();
    if (threadIdx.x == 0) {
        float s = 0.f;
        #pragma unroll
        for (int i = 0; i < 8; i++) s += red[i];
        atomicAdd(out, s / (float)B);
    }
}

// ---------------- launch ----------------
extern "C" void kernel_launch(void* const* d_in, const int* in_sizes, int n_in,
                              void* d_out, int out_size) {
    const float* x = (const float*)d_in[0];
    const float* W = (const float*)d_in[1];
    const void*  labels = d_in[2];
    float* out = (float*)d_out;

    int B = in_sizes[0] / D_DIM;
    int V = in_sizes[1] / D_DIM;
    int nvt = V / TN;                           // 250

    __nv_bfloat16 *nx, *nW;
    float *rowsum, *xinv, *winv;
    cudaGetSymbolAddress((void**)&nx, g_nx);
    cudaGetSymbolAddress((void**)&nW, g_nW);
    cudaGetSymbolAddress((void**)&rowsum, g_rowsum);
    cudaGetSymbolAddress((void**)&xinv, g_xinv);
    cudaGetSymbolAddress((void**)&winv, g_winv);

    cudaFuncSetAttribute(gemm_expsum_kernel,
                         cudaFuncAttributeMaxDynamicSharedMemorySize, SM_TOTAL);

    normalize_kernel<<<B + V + 1, 128>>>(x, W, nx, nW, rowsum, xinv, winv,
                                         (const int*)labels, out, B, V);
    gemm_expsum_kernel<<<dim3(NGROUP, B / TM), NTHR, SM_TOTAL>>>(nx, nW, rowsum, nvt);
    loss_kernel<<<(B + 7) / 8, 256>>>(x, W, labels, rowsum, xinv, winv, out, B);
}

// round 15
// speedup vs baseline: 1.1510x; 1.0427x over previous
#include <cuda_runtime.h>
#include <cuda_bf16.h>
#include <cstdint>
#include <math.h>

#define DEV_INLINE __device__ __forceinline__

// ---------------- problem constants ----------------
static constexpr int D_DIM = 512;
static constexpr int MAXB  = 2048;
static constexpr int MAXV  = 32000;
static constexpr float S_SCALE = 30.0f;
static constexpr float LOG2E   = 1.4426950408889634f;
static constexpr float S_LOG2E = S_SCALE * LOG2E;            // 43.2808...
static constexpr float COS_M = 0.8775825618903728f;          // cos(0.5)
static constexpr float SIN_M = 0.4794255386042030f;          // sin(0.5)

// ---------------- scratch (device globals; no cudaMalloc allowed) ----------------
__device__ __nv_bfloat16 g_nx[MAXB * D_DIM];
__device__ __nv_bfloat16 g_nW[MAXV * D_DIM];
__device__ float g_rowsum[MAXB];
__device__ float g_xinv[MAXB];
__device__ float g_winv[MAXV];
__device__ int   g_lab64;

// ---------------- PTX helpers (plain sm_103 ISA only) --------
DEV_INLINE uint32_t smem_u32(const void* p) {
    uint32_t a;
    asm("{ .reg .u64 t; cvta.to.shared.u64 t, %1; cvt.u32.u64 %0, t; }"
        : "=r"(a) : "l"(p));
    return a;
}

DEV_INLINE float ex2_fast(float x) {     // single MUFU.EX2
    float y;
    asm("ex2.approx.ftz.f32 %0, %1;" : "=f"(y) : "f"(x));
    return y;
}

DEV_INLINE void cp_async16(uint32_t saddr, const void* gptr) {
    asm volatile("cp.async.cg.shared.global [%0], [%1], 16;"
                 :: "r"(saddr), "l"(gptr) : "memory");
}
DEV_INLINE void cp_commit() { asm volatile("cp.async.commit_group;" ::: "memory"); }
template <int N>
DEV_INLINE void cp_wait() { asm volatile("cp.async.wait_group %0;" :: "n"(N) : "memory"); }

DEV_INLINE void ldsm_x4(uint32_t& r0, uint32_t& r1, uint32_t& r2, uint32_t& r3,
                        uint32_t addr) {
    asm volatile("ldmatrix.sync.aligned.m8n8.x4.shared.b16 {%0,%1,%2,%3}, [%4];"
                 : "=r"(r0), "=r"(r1), "=r"(r2), "=r"(r3) : "r"(addr));
}

DEV_INLINE void mma16816(float* c, const uint32_t* a, const uint32_t* b) {
    asm volatile(
        "mma.sync.aligned.m16n8k16.row.col.f32.bf16.bf16.f32 "
        "{%0,%1,%2,%3}, {%4,%5,%6,%7}, {%8,%9}, {%0,%1,%2,%3};"
        : "+f"(c[0]), "+f"(c[1]), "+f"(c[2]), "+f"(c[3])
        : "r"(a[0]), "r"(a[1]), "r"(a[2]), "r"(a[3]), "r"(b[0]), "r"(b[1]));
}

// ---------------- kernel 1: warp-per-row normalize + inv norms + misc -------
// Each warp normalizes one row of 512 floats: lane holds 16 values,
// warp-shuffle reduce, 4x8B coalesced bf16 stores. No smem, no barriers.
__global__ void normalize_kernel(const float* __restrict__ x,
                                 const float* __restrict__ W,
                                 __nv_bfloat16* __restrict__ nx,
                                 __nv_bfloat16* __restrict__ nW,
                                 float* __restrict__ rowsum,
                                 float* __restrict__ xinv,
                                 float* __restrict__ winv,
                                 const int* __restrict__ l32,
                                 float* __restrict__ out, int B, int V) {
    int gw = (int)((blockIdx.x * blockDim.x + threadIdx.x) >> 5);
    int lane = threadIdx.x & 31;
    int total = B + V;
    if (gw >= total) {                  // misc warp: label dtype + out zero
        if (gw == total) {
            int v = l32[2 * lane + 1];
            unsigned m = __ballot_sync(0xFFFFFFFFu, v == 0);
            if (lane == 0) { g_lab64 = (m == 0xFFFFFFFFu) ? 1 : 0; out[0] = 0.0f; }
        }
        return;
    }
    const float* in;
    __nv_bfloat16* outp;
    int r;
    if (gw < B) { in = x; outp = nx; r = gw; }
    else        { in = W; outp = nW; r = gw - B; }

    float4 v[4];
    float ss = 0.f;
    #pragma unroll
    for (int i = 0; i < 4; i++) {
        v[i] = *(const float4*)(in + (size_t)r * D_DIM + (lane + i * 32) * 4);
        ss += v[i].x * v[i].x + v[i].y * v[i].y + v[i].z * v[i].z + v[i].w * v[i].w;
    }
    #pragma unroll
    for (int o = 16; o; o >>= 1) ss += __shfl_xor_sync(0xFFFFFFFFu, ss, o);
    float inv = 1.0f / fmaxf(sqrtf(ss), 1e-12f);
    #pragma unroll
    for (int i = 0; i < 4; i++) {
        __nv_bfloat162 h0 = __floats2bfloat162_rn(v[i].x * inv, v[i].y * inv);
        __nv_bfloat162 h1 = __floats2bfloat162_rn(v[i].z * inv, v[i].w * inv);
        uint2 pk;
        pk.x = *(uint32_t*)&h0;
        pk.y = *(uint32_t*)&h1;
        *(uint2*)(outp + (size_t)r * D_DIM + (lane + i * 32) * 4) = pk;
    }
    if (lane == 0) {
        if (gw < B) { xinv[gw] = inv; rowsum[gw] = 0.0f; }
        else        { winv[r] = inv; }
    }
}

// ---------------- kernel 2 (R11 GEMM, unchanged): A-resident HMMA ----------
static constexpr int TM = 128;
static constexpr int TN = 128;
static constexpr int KC = 64;
static constexpr int KT = D_DIM / KC;          // 8
static constexpr int BSTAGES = 4;
static constexpr int NTHR = 256;
static constexpr int NGROUP = 9;               // 9*16 = 144 CTAs
static constexpr int A_BYTES = TM * D_DIM * 2;          // 131072
static constexpr int B_STAGE_BYTES = TN * KC * 2;       // 16384
static constexpr int SM_TOTAL = A_BYTES + BSTAGES * B_STAGE_BYTES;  // 196608

DEV_INLINE uint32_t a_off(int row, int k) {
    return (uint32_t)(row * 1024 + (((k >> 3) ^ (row & 7)) << 4) + ((k & 7) << 1));
}
DEV_INLINE uint32_t sw_off(int row, int k) {
    return (uint32_t)(row * 128 + (((k >> 3) ^ (row & 7)) << 4) + ((k & 7) << 1));
}

DEV_INLINE void load_b(uint32_t sbase, const __nv_bfloat16* __restrict__ src,
                       int n0, int k0, int tid) {
    #pragma unroll
    for (int i = 0; i < TN * 8 / NTHR; i++) {      // 4 iters
        int idx = i * NTHR + tid;
        int row = idx >> 3;
        int kc  = (idx & 7) << 3;
        cp_async16(sbase + sw_off(row, kc),
                   src + (size_t)(n0 + row) * D_DIM + k0 + kc);
    }
}

__global__ void __launch_bounds__(NTHR, 1)
gemm_expsum_kernel(const __nv_bfloat16* __restrict__ A,
                   const __nv_bfloat16* __restrict__ Bm,
                   float* __restrict__ rowsum, int nvt) {
    extern __shared__ char smem[];
    const uint32_t sa = smem_u32(smem);                 // A region
    const uint32_t sbB = sa + A_BYTES;                  // B ring base
    const int tid = threadIdx.x;
    const int wid = tid >> 5, lid = tid & 31;
    const int wm = wid & 1;          // 0..1 (M, 64 rows)
    const int wn = wid >> 1;         // 0..3 (N, 32 cols)
    const int m0 = blockIdx.y * TM;

    const int t0 = (blockIdx.x * nvt) / NGROUP;
    const int t1 = ((blockIdx.x + 1) * nvt) / NGROUP;
    if (t0 >= t1) return;

    // ---- load A tile once (128KB) ----
    #pragma unroll
    for (int i = 0; i < TM * 64 / NTHR; i++) {          // 32 iters
        int idx = i * NTHR + tid;
        int row = idx >> 6;
        int c   = idx & 63;
        cp_async16(sa + a_off(row, c * 8),
                   A + (size_t)(m0 + row) * D_DIM + c * 8);
    }
    cp_commit();

    // ---- B prologue: chunks 0,1,2 of first tile ----
    int n0 = t0 * TN;
    #pragma unroll
    for (int s = 0; s < BSTAGES - 1; s++) {
        load_b(sbB + s * B_STAGE_BYTES, Bm, n0, s * KC, tid);
        cp_commit();
    }

    const int a_row = wm * 64 + (lid & 15);
    const int a_kc  = (lid >> 4) << 3;
    const int b_row = wn * 32 + (lid & 15);
    const int b_kc  = (lid >> 4) << 3;

    float acc[4][4][4];
    #pragma unroll
    for (int i = 0; i < 4; i++)
        #pragma unroll
        for (int j = 0; j < 4; j++)
            #pragma unroll
            for (int q = 0; q < 4; q++) acc[i][j][q] = 0.f;

    int slot = 0;
    for (int t = t0; t < t1; t++) {
        const int nn0 = (t + 1 < t1) ? (t + 1) * TN : -1;
        #pragma unroll
        for (int kt = 0; kt < KT; kt++) {
            cp_wait<BSTAGES - 2>();
            __syncthreads();

            int ps = (slot + BSTAGES - 1) & (BSTAGES - 1);
            if (kt + BSTAGES - 1 < KT) {
                load_b(sbB + ps * B_STAGE_BYTES, Bm, n0, (kt + BSTAGES - 1) * KC, tid);
            } else if (nn0 >= 0) {
                load_b(sbB + ps * B_STAGE_BYTES, Bm, nn0, (kt + BSTAGES - 1 - KT) * KC, tid);
            }
            cp_commit();

            const uint32_t sbm = sbB + slot * B_STAGE_BYTES;
            const int kbase = kt * KC;

            #pragma unroll
            for (int ks = 0; ks < KC / 16; ks++) {
                uint32_t afr[4][4];
                #pragma unroll
                for (int mt = 0; mt < 4; mt++)
                    ldsm_x4(afr[mt][0], afr[mt][1], afr[mt][2], afr[mt][3],
                            sa + a_off(a_row + mt * 16, kbase + ks * 16 + a_kc));
                uint32_t bfr[2][4];
                #pragma unroll
                for (int np = 0; np < 2; np++)
                    ldsm_x4(bfr[np][0], bfr[np][1], bfr[np][2], bfr[np][3],
                            sbm + sw_off(b_row + np * 16, ks * 16 + b_kc));
                #pragma unroll
                for (int mt = 0; mt < 4; mt++)
                    #pragma unroll
                    for (int nt = 0; nt < 4; nt++)
                        mma16816(acc[mt][nt], afr[mt], &bfr[nt >> 1][(nt & 1) * 2]);
            }
            slot = (slot + 1) & (BSTAGES - 1);
        }

        #pragma unroll
        for (int mt = 0; mt < 4; mt++) {
            float s0 = 0.f, s1 = 0.f;
            #pragma unroll
            for (int nt = 0; nt < 4; nt++) {
                s0 += ex2_fast(acc[mt][nt][0] * S_LOG2E)
                    + ex2_fast(acc[mt][nt][1] * S_LOG2E);
                s1 += ex2_fast(acc[mt][nt][2] * S_LOG2E)
                    + ex2_fast(acc[mt][nt][3] * S_LOG2E);
                #pragma unroll
                for (int q = 0; q < 4; q++) acc[mt][nt][q] = 0.f;
            }
            s0 += __shfl_xor_sync(0xFFFFFFFFu, s0, 1);
            s0 += __shfl_xor_sync(0xFFFFFFFFu, s0, 2);
            s1 += __shfl_xor_sync(0xFFFFFFFFu, s1, 1);
            s1 += __shfl_xor_sync(0xFFFFFFFFu, s1, 2);
            if ((lid & 3) == 0) {
                int r = m0 + wm * 64 + mt * 16 + (lid >> 2);
                atomicAdd(&rowsum[r], s0);
                atomicAdd(&rowsum[r + 8], s1);
            }
        }
        n0 = nn0;
    }
}

// ---------------- kernel 3: fused label-cos + loss reduction ----------------
__global__ void loss_kernel(const float* __restrict__ x, const float* __restrict__ W,
                            const void* __restrict__ labels,
                            const float* __restrict__ rowsum,
                            const float* __restrict__ xinv,
                            const float* __restrict__ winv,
                            float* __restrict__ out, int B) {
    int warp = (int)((blockIdx.x * blockDim.x + threadIdx.x) >> 5);
    int lane = threadIdx.x & 31;
    int wloc = (int)(threadIdx.x >> 5);
    float contrib = 0.f;
    if (warp < B) {
        long long y;
        if (g_lab64) y = ((const long long*)labels)[warp];
        else         y = (long long)((const int*)labels)[warp];
        const float* xr = x + (size_t)warp * D_DIM;
        const float* wr = W + (size_t)y * D_DIM;
        float dot = 0.f;
        #pragma unroll
        for (int i = 0; i < 4; i++) {
            int k = (lane + i * 32) * 4;
            float4 a = *(const float4*)(xr + k);
            float4 b = *(const float4*)(wr + k);
            dot += a.x * b.x + a.y * b.y + a.z * b.z + a.w * b.w;
        }
        #pragma unroll
        for (int o = 16; o; o >>= 1)
            dot += __shfl_xor_sync(0xFFFFFFFFu, dot, o);
        if (lane == 0) {
            float c = dot * xinv[warp] * winv[(int)y];
            c = fminf(fmaxf(c, -1.f), 1.f);
            float sn = sqrtf(fmaxf(1.f - c * c, 0.f));
            float phi = c * COS_M - sn * SIN_M;
            float S = rowsum[warp] - exp2f(S_LOG2E * c) + exp2f(S_LOG2E * phi);
            contrib = logf(S) - S_SCALE * phi;
        }
    }
    __shared__ float red[8];
    if (lane == 0) red[wloc] = contrib;
    __syncthreads();
    if (threadIdx.x == 0) {
        float s = 0.f;
        #pragma unroll
        for (int i = 0; i < 8; i++) s += red[i];
        atomicAdd(out, s / (float)B);
    }
}

// ---------------- launch ----------------
extern "C" void kernel_launch(void* const* d_in, const int* in_sizes, int n_in,
                              void* d_out, int out_size) {
    const float* x = (const float*)d_in[0];
    const float* W = (const float*)d_in[1];
    const void*  labels = d_in[2];
    float* out = (float*)d_out;

    int B = in_sizes[0] / D_DIM;
    int V = in_sizes[1] / D_DIM;
    int nvt = V / TN;                           // 250

    __nv_bfloat16 *nx, *nW;
    float *rowsum, *xinv, *winv;
    cudaGetSymbolAddress((void**)&nx, g_nx);
    cudaGetSymbolAddress((void**)&nW, g_nW);
    cudaGetSymbolAddress((void**)&rowsum, g_rowsum);
    cudaGetSymbolAddress((void**)&xinv, g_xinv);
    cudaGetSymbolAddress((void**)&winv, g_winv);

    cudaFuncSetAttribute(gemm_expsum_kernel,
                         cudaFuncAttributeMaxDynamicSharedMemorySize, SM_TOTAL);

    int nwarps = B + V + 1;                     // +1 misc warp
    int nblocks = (nwarps * 32 + 255) / 256;
    normalize_kernel<<<nblocks, 256>>>(x, W, nx, nW, rowsum, xinv, winv,
                                       (const int*)labels, out, B, V);
    gemm_expsum_kernel<<<dim3(NGROUP, B / TM), NTHR, SM_TOTAL>>>(nx, nW, rowsum, nvt);
    loss_kernel<<<(B + 7) / 8, 256>>>(x, W, labels, rowsum, xinv, winv, out, B);
}

// round 16
// speedup vs baseline: 1.1530x; 1.0018x over previous
#include <cuda_runtime.h>
#include <cuda_bf16.h>
#include <cstdint>
#include <math.h>

#define DEV_INLINE __device__ __forceinline__

// ---------------- problem constants ----------------
static constexpr int D_DIM = 512;
static constexpr int MAXB  = 2048;
static constexpr int MAXV  = 32000;
static constexpr float S_SCALE = 30.0f;
static constexpr float LOG2E   = 1.4426950408889634f;
static constexpr float S_LOG2E = S_SCALE * LOG2E;            // 43.2808...
static constexpr float COS_M = 0.8775825618903728f;          // cos(0.5)
static constexpr float SIN_M = 0.4794255386042030f;          // sin(0.5)

// ---------------- scratch (device globals; no cudaMalloc allowed) ----------------
__device__ __nv_bfloat16 g_nx[MAXB * D_DIM];
__device__ __nv_bfloat16 g_nW[MAXV * D_DIM];
__device__ float g_rowsum[MAXB];
__device__ float g_cosy[MAXB];

// ---------------- PTX helpers (plain sm_103 ISA only) --------
DEV_INLINE uint32_t smem_u32(const void* p) {
    uint32_t a;
    asm("{ .reg .u64 t; cvta.to.shared.u64 t, %1; cvt.u32.u64 %0, t; }"
        : "=r"(a) : "l"(p));
    return a;
}

DEV_INLINE float ex2_fast(float x) {     // single MUFU.EX2
    float y;
    asm("ex2.approx.ftz.f32 %0, %1;" : "=f"(y) : "f"(x));
    return y;
}

DEV_INLINE void cp_async16(uint32_t saddr, const void* gptr) {
    asm volatile("cp.async.cg.shared.global [%0], [%1], 16;"
                 :: "r"(saddr), "l"(gptr) : "memory");
}
DEV_INLINE void cp_commit() { asm volatile("cp.async.commit_group;" ::: "memory"); }
template <int N>
DEV_INLINE void cp_wait() { asm volatile("cp.async.wait_group %0;" :: "n"(N) : "memory"); }

DEV_INLINE void ldsm_x4(uint32_t& r0, uint32_t& r1, uint32_t& r2, uint32_t& r3,
                        uint32_t addr) {
    asm volatile("ldmatrix.sync.aligned.m8n8.x4.shared.b16 {%0,%1,%2,%3}, [%4];"
                 : "=r"(r0), "=r"(r1), "=r"(r2), "=r"(r3) : "r"(addr));
}

DEV_INLINE void mma16816(float* c, const uint32_t* a, const uint32_t* b) {
    asm volatile(
        "mma.sync.aligned.m16n8k16.row.col.f32.bf16.bf16.f32 "
        "{%0,%1,%2,%3}, {%4,%5,%6,%7}, {%8,%9}, {%0,%1,%2,%3};"
        : "+f"(c[0]), "+f"(c[1]), "+f"(c[2]), "+f"(c[3])
        : "r"(a[0]), "r"(a[1]), "r"(a[2]), "r"(a[3]), "r"(b[0]), "r"(b[1]));
}

// ---------------- kernel 1: normalize (warp/row) + label-cos warps ----------
// Warps [0, B+V): normalize one row (shuffle reduce, no smem/barriers).
// Warps [B+V, B+V+B): exact fp32 cos at the label column (3-way reduction on
// raw x/W; label dtype detected per-warp via ballot on the first 64 words).
__global__ void normalize_kernel(const float* __restrict__ x,
                                 const float* __restrict__ W,
                                 __nv_bfloat16* __restrict__ nx,
                                 __nv_bfloat16* __restrict__ nW,
                                 float* __restrict__ rowsum,
                                 float* __restrict__ cosy,
                                 const void* __restrict__ labels,
                                 int B, int V) {
    int gw = (int)((blockIdx.x * blockDim.x + threadIdx.x) >> 5);
    int lane = threadIdx.x & 31;
    int total = B + V;

    if (gw >= total) {                           // label-cos warp
        int b = gw - total;
        if (b >= B) return;
        const int* l32 = (const int*)labels;
        int vv = l32[2 * lane + 1];
        unsigned m = __ballot_sync(0xFFFFFFFFu, vv == 0);
        bool lab64 = (m == 0xFFFFFFFFu);
        long long y = lab64 ? ((const long long*)labels)[b]
                            : (long long)l32[b];
        const float* xr = x + (size_t)b * D_DIM;
        const float* wr = W + (size_t)y * D_DIM;
        float dot = 0.f, xx = 0.f, ww = 0.f;
        #pragma unroll
        for (int i = 0; i < 4; i++) {
            int k = (lane + i * 32) * 4;
            float4 a = *(const float4*)(xr + k);
            float4 bb = *(const float4*)(wr + k);
            dot += a.x * bb.x + a.y * bb.y + a.z * bb.z + a.w * bb.w;
            xx  += a.x * a.x + a.y * a.y + a.z * a.z + a.w * a.w;
            ww  += bb.x * bb.x + bb.y * bb.y + bb.z * bb.z + bb.w * bb.w;
        }
        #pragma unroll
        for (int o = 16; o; o >>= 1) {
            dot += __shfl_xor_sync(0xFFFFFFFFu, dot, o);
            xx  += __shfl_xor_sync(0xFFFFFFFFu, xx, o);
            ww  += __shfl_xor_sync(0xFFFFFFFFu, ww, o);
        }
        if (lane == 0)
            cosy[b] = dot / (fmaxf(sqrtf(xx), 1e-12f) * fmaxf(sqrtf(ww), 1e-12f));
        return;
    }

    const float* in;
    __nv_bfloat16* outp;
    int r;
    if (gw < B) { in = x; outp = nx; r = gw; }
    else        { in = W; outp = nW; r = gw - B; }

    float4 v[4];
    float ss = 0.f;
    #pragma unroll
    for (int i = 0; i < 4; i++) {
        v[i] = *(const float4*)(in + (size_t)r * D_DIM + (lane + i * 32) * 4);
        ss += v[i].x * v[i].x + v[i].y * v[i].y + v[i].z * v[i].z + v[i].w * v[i].w;
    }
    #pragma unroll
    for (int o = 16; o; o >>= 1) ss += __shfl_xor_sync(0xFFFFFFFFu, ss, o);
    float inv = 1.0f / fmaxf(sqrtf(ss), 1e-12f);
    #pragma unroll
    for (int i = 0; i < 4; i++) {
        __nv_bfloat162 h0 = __floats2bfloat162_rn(v[i].x * inv, v[i].y * inv);
        __nv_bfloat162 h1 = __floats2bfloat162_rn(v[i].z * inv, v[i].w * inv);
        uint2 pk;
        pk.x = *(uint32_t*)&h0;
        pk.y = *(uint32_t*)&h1;
        *(uint2*)(outp + (size_t)r * D_DIM + (lane + i * 32) * 4) = pk;
    }
    if (gw < B && lane == 0) rowsum[gw] = 0.0f;
}

// ---------------- kernel 2 (R11 GEMM, unchanged): A-resident HMMA ----------
static constexpr int TM = 128;
static constexpr int TN = 128;
static constexpr int KC = 64;
static constexpr int KT = D_DIM / KC;          // 8
static constexpr int BSTAGES = 4;
static constexpr int NTHR = 256;
static constexpr int NGROUP = 9;               // 9*16 = 144 CTAs
static constexpr int A_BYTES = TM * D_DIM * 2;          // 131072
static constexpr int B_STAGE_BYTES = TN * KC * 2;       // 16384
static constexpr int SM_TOTAL = A_BYTES + BSTAGES * B_STAGE_BYTES;  // 196608

DEV_INLINE uint32_t a_off(int row, int k) {
    return (uint32_t)(row * 1024 + (((k >> 3) ^ (row & 7)) << 4) + ((k & 7) << 1));
}
DEV_INLINE uint32_t sw_off(int row, int k) {
    return (uint32_t)(row * 128 + (((k >> 3) ^ (row & 7)) << 4) + ((k & 7) << 1));
}

DEV_INLINE void load_b(uint32_t sbase, const __nv_bfloat16* __restrict__ src,
                       int n0, int k0, int tid) {
    #pragma unroll
    for (int i = 0; i < TN * 8 / NTHR; i++) {      // 4 iters
        int idx = i * NTHR + tid;
        int row = idx >> 3;
        int kc  = (idx & 7) << 3;
        cp_async16(sbase + sw_off(row, kc),
                   src + (size_t)(n0 + row) * D_DIM + k0 + kc);
    }
}

__global__ void __launch_bounds__(NTHR, 1)
gemm_expsum_kernel(const __nv_bfloat16* __restrict__ A,
                   const __nv_bfloat16* __restrict__ Bm,
                   float* __restrict__ rowsum, int nvt) {
    extern __shared__ char smem[];
    const uint32_t sa = smem_u32(smem);                 // A region
    const uint32_t sbB = sa + A_BYTES;                  // B ring base
    const int tid = threadIdx.x;
    const int wid = tid >> 5, lid = tid & 31;
    const int wm = wid & 1;          // 0..1 (M, 64 rows)
    const int wn = wid >> 1;         // 0..3 (N, 32 cols)
    const int m0 = blockIdx.y * TM;

    const int t0 = (blockIdx.x * nvt) / NGROUP;
    const int t1 = ((blockIdx.x + 1) * nvt) / NGROUP;
    if (t0 >= t1) return;

    // ---- load A tile once (128KB) ----
    #pragma unroll
    for (int i = 0; i < TM * 64 / NTHR; i++) {          // 32 iters
        int idx = i * NTHR + tid;
        int row = idx >> 6;
        int c   = idx & 63;
        cp_async16(sa + a_off(row, c * 8),
                   A + (size_t)(m0 + row) * D_DIM + c * 8);
    }
    cp_commit();

    // ---- B prologue: chunks 0,1,2 of first tile ----
    int n0 = t0 * TN;
    #pragma unroll
    for (int s = 0; s < BSTAGES - 1; s++) {
        load_b(sbB + s * B_STAGE_BYTES, Bm, n0, s * KC, tid);
        cp_commit();
    }

    const int a_row = wm * 64 + (lid & 15);
    const int a_kc  = (lid >> 4) << 3;
    const int b_row = wn * 32 + (lid & 15);
    const int b_kc  = (lid >> 4) << 3;

    float acc[4][4][4];
    #pragma unroll
    for (int i = 0; i < 4; i++)
        #pragma unroll
        for (int j = 0; j < 4; j++)
            #pragma unroll
            for (int q = 0; q < 4; q++) acc[i][j][q] = 0.f;

    int slot = 0;
    for (int t = t0; t < t1; t++) {
        const int nn0 = (t + 1 < t1) ? (t + 1) * TN : -1;
        #pragma unroll
        for (int kt = 0; kt < KT; kt++) {
            cp_wait<BSTAGES - 2>();
            __syncthreads();

            int ps = (slot + BSTAGES - 1) & (BSTAGES - 1);
            if (kt + BSTAGES - 1 < KT) {
                load_b(sbB + ps * B_STAGE_BYTES, Bm, n0, (kt + BSTAGES - 1) * KC, tid);
            } else if (nn0 >= 0) {
                load_b(sbB + ps * B_STAGE_BYTES, Bm, nn0, (kt + BSTAGES - 1 - KT) * KC, tid);
            }
            cp_commit();

            const uint32_t sbm = sbB + slot * B_STAGE_BYTES;
            const int kbase = kt * KC;

            #pragma unroll
            for (int ks = 0; ks < KC / 16; ks++) {
                uint32_t afr[4][4];
                #pragma unroll
                for (int mt = 0; mt < 4; mt++)
                    ldsm_x4(afr[mt][0], afr[mt][1], afr[mt][2], afr[mt][3],
                            sa + a_off(a_row + mt * 16, kbase + ks * 16 + a_kc));
                uint32_t bfr[2][4];
                #pragma unroll
                for (int np = 0; np < 2; np++)
                    ldsm_x4(bfr[np][0], bfr[np][1], bfr[np][2], bfr[np][3],
                            sbm + sw_off(b_row + np * 16, ks * 16 + b_kc));
                #pragma unroll
                for (int mt = 0; mt < 4; mt++)
                    #pragma unroll
                    for (int nt = 0; nt < 4; nt++)
                        mma16816(acc[mt][nt], afr[mt], &bfr[nt >> 1][(nt & 1) * 2]);
            }
            slot = (slot + 1) & (BSTAGES - 1);
        }

        #pragma unroll
        for (int mt = 0; mt < 4; mt++) {
            float s0 = 0.f, s1 = 0.f;
            #pragma unroll
            for (int nt = 0; nt < 4; nt++) {
                s0 += ex2_fast(acc[mt][nt][0] * S_LOG2E)
                    + ex2_fast(acc[mt][nt][1] * S_LOG2E);
                s1 += ex2_fast(acc[mt][nt][2] * S_LOG2E)
                    + ex2_fast(acc[mt][nt][3] * S_LOG2E);
                #pragma unroll
                for (int q = 0; q < 4; q++) acc[mt][nt][q] = 0.f;
            }
            s0 += __shfl_xor_sync(0xFFFFFFFFu, s0, 1);
            s0 += __shfl_xor_sync(0xFFFFFFFFu, s0, 2);
            s1 += __shfl_xor_sync(0xFFFFFFFFu, s1, 1);
            s1 += __shfl_xor_sync(0xFFFFFFFFu, s1, 2);
            if ((lid & 3) == 0) {
                int r = m0 + wm * 64 + mt * 16 + (lid >> 2);
                atomicAdd(&rowsum[r], s0);
                atomicAdd(&rowsum[r + 8], s1);
            }
        }
        n0 = nn0;
    }
}

// ---------------- kernel 3: finalize (single block, no atomics) -------------
__global__ void finalize_kernel(const float* __restrict__ rowsum,
                                const float* __restrict__ cosy,
                                float* __restrict__ out, int B) {
    __shared__ float red[1024];
    int tid = threadIdx.x;
    float local = 0.f;
    for (int b = tid; b < B; b += 1024) {
        float c  = fminf(fmaxf(cosy[b], -1.f), 1.f);
        float sn = sqrtf(fmaxf(1.f - c * c, 0.f));
        float phi = c * COS_M - sn * SIN_M;
        float S = rowsum[b] - exp2f(S_LOG2E * c) + exp2f(S_LOG2E * phi);
        local += logf(S) - S_SCALE * phi;
    }
    red[tid] = local;
    __syncthreads();
    #pragma unroll
    for (int s = 512; s > 0; s >>= 1) {
        if (tid < s) red[tid] += red[tid + s];
        __syncthreads();
    }
    if (tid == 0) out[0] = red[0] / (float)B;
}

// ---------------- launch ----------------
extern "C" void kernel_launch(void* const* d_in, const int* in_sizes, int n_in,
                              void* d_out, int out_size) {
    const float* x = (const float*)d_in[0];
    const float* W = (const float*)d_in[1];
    const void*  labels = d_in[2];
    float* out = (float*)d_out;

    int B = in_sizes[0] / D_DIM;
    int V = in_sizes[1] / D_DIM;
    int nvt = V / TN;                           // 250

    __nv_bfloat16 *nx, *nW;
    float *rowsum, *cosy;
    cudaGetSymbolAddress((void**)&nx, g_nx);
    cudaGetSymbolAddress((void**)&nW, g_nW);
    cudaGetSymbolAddress((void**)&rowsum, g_rowsum);
    cudaGetSymbolAddress((void**)&cosy, g_cosy);

    cudaFuncSetAttribute(gemm_expsum_kernel,
                         cudaFuncAttributeMaxDynamicSharedMemorySize, SM_TOTAL);

    int nwarps = B + V + B;                     // normalize + cosy warps
    int nblocks = (nwarps * 32 + 255) / 256;
    normalize_kernel<<<nblocks, 256>>>(x, W, nx, nW, rowsum, cosy, labels, B, V);
    gemm_expsum_kernel<<<dim3(NGROUP, B / TM), NTHR, SM_TOTAL>>>(nx, nW, rowsum, nvt);
    finalize_kernel<<<1, 1024>>>(rowsum, cosy, out, B);
}